// round 5
// baseline (speedup 1.0000x reference)
#include <cuda_runtime.h>
#include <math.h>

constexpr int H = 256;
constexpr int B = 4;
constexpr int S = 128;
constexpr int T = 128;

typedef unsigned long long ull;

// Scratch (device globals — no allocation allowed)
__device__ float g_pre_x[(size_t)B * S * T * H];
__device__ float g_pre_y[(size_t)B * S * T * H];
__device__ float g_hx  [(size_t)B * S * T * H];
__device__ float g_hy  [(size_t)B * S * T * H];
__device__ float g_psx [(size_t)B * S * H];
__device__ float g_psy [(size_t)B * T * H];
__device__ unsigned g_flags[128];   // [path(2)][rowtile(16)][coltile(4)]

// ---------------- packed f32x2 helpers ----------------
__device__ __forceinline__ ull pack2(float x) {
    ull r; asm("mov.b64 %0, {%1, %1};" : "=l"(r) : "f"(x)); return r;
}
__device__ __forceinline__ void ffma2(ull& d, ull a, ull b) {
    asm("fma.rn.f32x2 %0, %1, %2, %0;" : "+l"(d) : "l"(a), "l"(b));
}
__device__ __forceinline__ float2 unpack2(ull v) {
    float2 f; asm("mov.b64 {%0, %1}, %2;" : "=f"(f.x), "=f"(f.y) : "l"(v)); return f;
}
__device__ __forceinline__ unsigned ld_acq(const unsigned* p) {
    unsigned v;
    asm volatile("ld.global.acquire.gpu.u32 %0, [%1];" : "=r"(v) : "l"(p) : "memory");
    return v;
}
__device__ __forceinline__ void st_rel(unsigned* p, unsigned v) {
    asm volatile("st.global.release.gpu.u32 [%0], %1;" :: "l"(p), "r"(v) : "memory");
}

// Accurate tanh regardless of --use_fast_math
__device__ __forceinline__ float my_tanh(float x) {
    float ax = fabsf(x);
    float e  = expf(-2.0f * ax);
    float t  = (1.0f - e) / (1.0f + e);
    return x < 0.0f ? -t : t;
}

__global__ void reset_flags_kernel() { g_flags[threadIdx.x] = 0; }

// ---------------------------------------------------------------------------
// Prepass GEMM (f32x2): C[m,n] = sum_k A[m,k]*W[n,k] + b1[n] + b2[n]
// N=K=256. BM=BN=64, BK=32, 256 thr, 4 rows x 4 cols per thread.
// A staged duplicated ({v,v}) so FFMA2 broadcast operand is one LDS.64.
// ---------------------------------------------------------------------------
__global__ void __launch_bounds__(256) gemm256_bias(
    const float* __restrict__ A, const float* __restrict__ W,
    const float* __restrict__ b1, const float* __restrict__ b2,
    float* __restrict__ C)
{
    __shared__ float As[32 * 132];   // [k][2*m], duplicated pairs
    __shared__ float Bs[32 * 68];    // [k][n]

    const int m0  = blockIdx.x << 6;
    const int n0  = blockIdx.y << 6;
    const int tid = threadIdx.x;
    const int tx  = tid & 15;        // n sub-tile (4 cols)
    const int ty  = tid >> 4;        // m sub-tile (4 rows)
    const int lr  = tid >> 2;        // 0..63 load row
    const int lk  = (tid & 3) << 2;  // 0,4,8,12

    const float* Ap = A + (size_t)(m0 + lr) * H + lk;
    const float* Wp = W + (size_t)(n0 + lr) * H + lk;

    float4 ra0 = *(const float4*)(Ap);
    float4 ra1 = *(const float4*)(Ap + 16);
    float4 rw0 = *(const float4*)(Wp);
    float4 rw1 = *(const float4*)(Wp + 16);

    ull acc[4][2] = {};

    for (int c = 0; c < 8; c++) {
        *(float2*)&As[(lk + 0) * 132 + (lr << 1)] = make_float2(ra0.x, ra0.x);
        *(float2*)&As[(lk + 1) * 132 + (lr << 1)] = make_float2(ra0.y, ra0.y);
        *(float2*)&As[(lk + 2) * 132 + (lr << 1)] = make_float2(ra0.z, ra0.z);
        *(float2*)&As[(lk + 3) * 132 + (lr << 1)] = make_float2(ra0.w, ra0.w);
        *(float2*)&As[(lk + 16) * 132 + (lr << 1)] = make_float2(ra1.x, ra1.x);
        *(float2*)&As[(lk + 17) * 132 + (lr << 1)] = make_float2(ra1.y, ra1.y);
        *(float2*)&As[(lk + 18) * 132 + (lr << 1)] = make_float2(ra1.z, ra1.z);
        *(float2*)&As[(lk + 19) * 132 + (lr << 1)] = make_float2(ra1.w, ra1.w);
        Bs[(lk + 0) * 68 + lr] = rw0.x;  Bs[(lk + 1) * 68 + lr] = rw0.y;
        Bs[(lk + 2) * 68 + lr] = rw0.z;  Bs[(lk + 3) * 68 + lr] = rw0.w;
        Bs[(lk + 16) * 68 + lr] = rw1.x; Bs[(lk + 17) * 68 + lr] = rw1.y;
        Bs[(lk + 18) * 68 + lr] = rw1.z; Bs[(lk + 19) * 68 + lr] = rw1.w;
        __syncthreads();

        if (c < 7) {
            int k = (c + 1) << 5;
            ra0 = *(const float4*)(Ap + k);
            ra1 = *(const float4*)(Ap + k + 16);
            rw0 = *(const float4*)(Wp + k);
            rw1 = *(const float4*)(Wp + k + 16);
        }

        const float* aB = As + (ty << 3);   // ty*4 rows, duplicated
        const float* bB = Bs + (tx << 2);
        #pragma unroll
        for (int kk = 0; kk < 32; kk++) {
            ull a0 = *(const ull*)(aB + kk * 132);
            ull a1 = *(const ull*)(aB + kk * 132 + 2);
            ull a2 = *(const ull*)(aB + kk * 132 + 4);
            ull a3 = *(const ull*)(aB + kk * 132 + 6);
            ulonglong2 bb = *(const ulonglong2*)(bB + kk * 68);
            ffma2(acc[0][0], a0, bb.x); ffma2(acc[0][1], a0, bb.y);
            ffma2(acc[1][0], a1, bb.x); ffma2(acc[1][1], a1, bb.y);
            ffma2(acc[2][0], a2, bb.x); ffma2(acc[2][1], a2, bb.y);
            ffma2(acc[3][0], a3, bb.x); ffma2(acc[3][1], a3, bb.y);
        }
        __syncthreads();
    }

    const int n = n0 + (tx << 2);
    float4 bv;
    bv.x = b1[n + 0] + b2[n + 0];
    bv.y = b1[n + 1] + b2[n + 1];
    bv.z = b1[n + 2] + b2[n + 2];
    bv.w = b1[n + 3] + b2[n + 3];

    #pragma unroll
    for (int i = 0; i < 4; i++) {
        float2 p0 = unpack2(acc[i][0]);
        float2 p1 = unpack2(acc[i][1]);
        float4 o;
        o.x = p0.x + bv.x;  o.y = p0.y + bv.y;
        o.z = p1.x + bv.z;  o.w = p1.y + bv.w;
        *(float4*)(C + (size_t)(m0 + (ty << 2) + i) * H + n) = o;
    }
}

// ---------------------------------------------------------------------------
// Persistent recurrence kernel: one launch per depth, 128 steps inside.
// Grid (4 coltiles, 16 rowtiles, 2 paths) = 128 CTAs, 1/SM, all co-resident.
// W_hh tile (64 cols x 256 k) resident in SMEM for the whole depth.
// Cross-step ordering via release/acquire flags in L2 (one per tile).
// ---------------------------------------------------------------------------
struct RArgs {
    const float* W;
    const float* pre; int p_sstep, p_sb, p_sq;
    float*       out; int o_sstep, o_sb, o_sq;
};

constexpr int RECUR_SMEM = (256 * 68 + 256 * 68) * 4;   // Ws + As(dup) = 136 KB

__global__ void __launch_bounds__(256, 1) recur_depth(RArgs AX, RArgs AY, int flag_base)
{
    extern __shared__ float smem_[];
    float* Ws = smem_;               // [k=256][n=64 + pad] stride 68
    float* As = smem_ + 256 * 68;    // [k=256][2*32 rows + pad] stride 68, duplicated

    const int path = blockIdx.z;
    const RArgs P = path ? AY : AX;
    const int bx  = blockIdx.x;      // col tile 0..3
    const int by  = blockIdx.y;      // row tile 0..15
    const int tid = threadIdx.x;
    // lane remap: warp covers 8 tx x 4 ty -> smem crossbar 192B/warp/k
    const int tx  = (tid & 7) | ((tid >> 4) & 8);          // 0..15 (4 cols each)
    const int ty  = ((tid >> 3) & 3) | (((tid >> 5) & 3) << 2); // 0..15 (2 rows each)
    const int n0  = bx << 6;
    const int b   = by >> 2;           // batch
    const int q0  = (by & 3) << 5;     // row offset within batch

    // ---- load W tile into SMEM (once per depth) ----
    {
        const int wr = tid >> 2, wlk = (tid & 3) << 2;
        const float* Wp = P.W + (size_t)(n0 + wr) * H + wlk;
        #pragma unroll
        for (int c = 0; c < 8; c++) {
            float4 w0 = *(const float4*)(Wp + (c << 5));
            float4 w1 = *(const float4*)(Wp + (c << 5) + 16);
            const int k = (c << 5) + wlk;
            Ws[(k + 0) * 68 + wr] = w0.x;  Ws[(k + 1) * 68 + wr] = w0.y;
            Ws[(k + 2) * 68 + wr] = w0.z;  Ws[(k + 3) * 68 + wr] = w0.w;
            Ws[(k + 16) * 68 + wr] = w1.x; Ws[(k + 17) * 68 + wr] = w1.y;
            Ws[(k + 18) * 68 + wr] = w1.z; Ws[(k + 19) * 68 + wr] = w1.w;
        }
    }

    // ---- flag wiring ----
    unsigned* myFlag = &g_flags[(path * 16 + by) * 4 + bx];
    const unsigned* pollPtr = nullptr;
    if (path == 0) {
        // x-path: own row tile (4 col flags) + wrapped-neighbor row tile (4)
        if (tid < 8) {
            int byp = (tid < 4) ? by : ((by & 12) | (((by & 3) + 3) & 3));
            pollPtr = &g_flags[byp * 4 + (tid & 3)];
        }
    } else {
        if (tid < 4) pollPtr = &g_flags[(16 + by) * 4 + tid];
    }

    const int ar  = tid >> 3;          // 0..31 state row
    const int alk = (tid & 7) << 2;    // 0..28
    const int qs  = (path == 0) ? ((q0 + ar + 127) & 127) : (q0 + ar);
    const int qr  = q0 + (ty << 1);

    __syncthreads();

    for (int st = 0; st < 128; st++) {
        // prefetch pre (independent of flags; hides DRAM latency under poll+GEMM)
        const float* pp = P.pre + (size_t)st * P.p_sstep + (size_t)b * P.p_sb
                                + n0 + (tx << 2);
        const float4 pv0 = *(const float4*)(pp + (size_t)qr * P.p_sq);
        const float4 pv1 = *(const float4*)(pp + (size_t)(qr + 1) * P.p_sq);

        ull acc00 = 0, acc01 = 0, acc10 = 0, acc11 = 0;

        if (st > 0) {
            if (pollPtr) {
                const unsigned tgt = (unsigned)(flag_base + st);
                while (ld_acq(pollPtr) < tgt) { }
            }
            __syncthreads();

            // stage state rows (duplicated {v,v}) into As
            const float* sp = P.out + (size_t)(st - 1) * P.o_sstep
                                    + (size_t)b * P.o_sb + (size_t)qs * P.o_sq + alk;
            #pragma unroll
            for (int c = 0; c < 8; c++) {
                float4 v = *(const float4*)(sp + (c << 5));
                const int k = (c << 5) + alk;
                *(float2*)&As[(k + 0) * 68 + (ar << 1)] = make_float2(v.x, v.x);
                *(float2*)&As[(k + 1) * 68 + (ar << 1)] = make_float2(v.y, v.y);
                *(float2*)&As[(k + 2) * 68 + (ar << 1)] = make_float2(v.z, v.z);
                *(float2*)&As[(k + 3) * 68 + (ar << 1)] = make_float2(v.w, v.w);
            }
            __syncthreads();

            // 32x64x256 tile GEMM, FFMA2 inner loop
            const float* aB = As + (ty << 2);
            const float* bB = Ws + (tx << 2);
            #pragma unroll 16
            for (int kk = 0; kk < 256; kk++) {
                ull a0 = *(const ull*)(aB + kk * 68);
                ull a1 = *(const ull*)(aB + kk * 68 + 2);
                ulonglong2 bb = *(const ulonglong2*)(bB + kk * 68);
                ffma2(acc00, a0, bb.x); ffma2(acc01, a0, bb.y);
                ffma2(acc10, a1, bb.x); ffma2(acc11, a1, bb.y);
            }
        }

        // epilogue: tanh(acc + pre) -> out
        float2 r00 = unpack2(acc00), r01 = unpack2(acc01);
        float2 r10 = unpack2(acc10), r11 = unpack2(acc11);
        float4 o0, o1;
        o0.x = my_tanh(r00.x + pv0.x); o0.y = my_tanh(r00.y + pv0.y);
        o0.z = my_tanh(r01.x + pv0.z); o0.w = my_tanh(r01.y + pv0.w);
        o1.x = my_tanh(r10.x + pv1.x); o1.y = my_tanh(r10.y + pv1.y);
        o1.z = my_tanh(r11.x + pv1.z); o1.w = my_tanh(r11.y + pv1.w);

        float* op = P.out + (size_t)st * P.o_sstep + (size_t)b * P.o_sb + n0 + (tx << 2);
        *(float4*)(op + (size_t)qr * P.o_sq)       = o0;
        *(float4*)(op + (size_t)(qr + 1) * P.o_sq) = o1;

        __threadfence();
        __syncthreads();
        if (tid == 0) st_rel(myFlag, (unsigned)(flag_base + st + 1));
    }
}

// ---------------------------------------------------------------------------
// Host orchestration: 10 launches total (flag reset + 3x(prepass + recur)).
// ---------------------------------------------------------------------------
extern "C" void kernel_launch(void* const* d_in, const int* in_sizes, int n_in,
                              void* d_out, int out_size)
{
    const float* src   = (const float*)d_in[0];
    const float* trg   = (const float*)d_in[1];
    const float* Wx_ih = (const float*)d_in[2];
    const float* Wx_hh = (const float*)d_in[3];
    const float* bx_ih = (const float*)d_in[4];
    const float* bx_hh = (const float*)d_in[5];
    const float* Wy_ih = (const float*)d_in[6];
    const float* Wy_hh = (const float*)d_in[7];
    const float* by_ih = (const float*)d_in[8];
    const float* by_hh = (const float*)d_in[9];
    float* out = (float*)d_out;

    float *pre_x, *pre_y, *hx, *hy, *psx, *psy;
    cudaGetSymbolAddress((void**)&pre_x, g_pre_x);
    cudaGetSymbolAddress((void**)&pre_y, g_pre_y);
    cudaGetSymbolAddress((void**)&hx,    g_hx);
    cudaGetSymbolAddress((void**)&hy,    g_hy);
    cudaGetSymbolAddress((void**)&psx,   g_psx);
    cudaGetSymbolAddress((void**)&psy,   g_psy);

    cudaFuncSetAttribute(recur_depth,
                         cudaFuncAttributeMaxDynamicSharedMemorySize, RECUR_SMEM);

    reset_flags_kernel<<<1, 128>>>();

    for (int d = 0; d < 3; d++) {
        // ---- prepass: input projection + fused biases ----
        if (d == 0) {
            gemm256_bias<<<dim3(B * S / 64, H / 64), 256>>>(src, Wx_ih, bx_ih, bx_hh, psx);
            gemm256_bias<<<dim3(B * T / 64, H / 64), 256>>>(trg, Wy_ih, by_ih, by_hh, psy);
        } else {
            gemm256_bias<<<dim3(B * S * T / 64, H / 64), 256>>>(
                hx, Wx_ih + (size_t)d * H * H, bx_ih + d * H, bx_hh + d * H, pre_x);
            gemm256_bias<<<dim3(B * S * T / 64, H / 64), 256>>>(
                hy, Wy_ih + (size_t)d * H * H, by_ih + d * H, by_hh + d * H, pre_y);
        }

        const int OS = (d == 2) ? 2 * H : H;   // per-(i,j) row stride
        float* Ox = (d == 2) ? out     : hx;   // slot 0
        float* Oy = (d == 2) ? out + H : hy;   // slot 1

        RArgs AX, AY;
        AX.W = Wx_hh + (size_t)d * H * H;
        AX.out = Ox; AX.o_sstep = T * OS; AX.o_sb = S * T * OS; AX.o_sq = OS;
        if (d == 0) { AX.pre = psx;   AX.p_sstep = H;     AX.p_sb = S * H;     AX.p_sq = 0; }
        else        { AX.pre = pre_x; AX.p_sstep = T * H; AX.p_sb = S * T * H; AX.p_sq = H; }

        AY.W = Wy_hh + (size_t)d * H * H;
        AY.out = Oy; AY.o_sstep = OS; AY.o_sb = S * T * OS; AY.o_sq = T * OS;
        if (d == 0) { AY.pre = psy;   AY.p_sstep = H; AY.p_sb = T * H;     AY.p_sq = 0;     }
        else        { AY.pre = pre_y; AY.p_sstep = H; AY.p_sb = S * T * H; AY.p_sq = T * H; }

        recur_depth<<<dim3(4, 16, 2), 256, RECUR_SMEM>>>(AX, AY, d * 128);
    }
}